// round 3
// baseline (speedup 1.0000x reference)
#include <cuda_runtime.h>
#include <cuda_bf16.h>
#include <math.h>

// Problem constants
#define TT   1024
#define BB   64
#define INF  256
#define HH   512
#define OUTF 256
#define G3   1536           // 3*H
#define BH   (BB*HH)        // 32768
#define BH3  (BB*G3)        // 98304
#define NCTA 128            // recurrence grid (<= 148 SMs -> co-resident)

// ---------------- scratch (no allocations allowed) ----------------
__device__ float    g_gi[(size_t)TT * BH3];   // [T,B,3H] input-side gate projections (402 MB)
__device__ float    g_h[2 * BH];              // double-buffered hidden state
__device__ unsigned g_bar;                    // grid-barrier arrival counter

// =====================================================================
// Kernel 1: gi[t,b,g] = sum_i x[b,t,i] * W_ih[g,i] + b_ih[g]
// GEMM: M = T*B (row m = t*64 + b), N = 1536, K = 256
// Tile: BM=128, BN=64, BK=16, 256 threads, 8x4 per-thread microtile.
// =====================================================================
__global__ __launch_bounds__(256) void gi_gemm_kernel(
    const float* __restrict__ x,
    const float* __restrict__ wih,
    const float* __restrict__ bih,
    float* __restrict__ gi)
{
    __shared__ float As[16 * 132];   // [k][m], padded row stride 132 (16B-aligned rows)
    __shared__ float Bs[16 * 68];    // [k][n], padded row stride 68

    const int tid = threadIdx.x;
    const int m0  = blockIdx.y * 128;
    const int n0  = blockIdx.x * 64;
    const int ty  = tid >> 4;        // 0..15 -> rows ty*8..ty*8+7
    const int tx  = tid & 15;        // 0..15 -> cols tx*4..tx*4+3

    float acc[8][4];
    #pragma unroll
    for (int i = 0; i < 8; i++)
        #pragma unroll
        for (int j = 0; j < 4; j++) acc[i][j] = 0.f;

    for (int k0 = 0; k0 < INF; k0 += 16) {
        // Load A tile 128x16 (transposed into smem). Row m -> x row (b*T + t).
        #pragma unroll
        for (int it = 0; it < 2; it++) {
            int L  = tid + it * 256;          // 0..511 (float4 slots)
            int r  = L >> 2;                  // 0..127
            int kq = L & 3;                   // 0..3
            int m  = m0 + r;
            int t  = m >> 6;
            int b  = m & 63;
            float4 v = *reinterpret_cast<const float4*>(
                &x[((size_t)b * TT + t) * INF + k0 + kq * 4]);
            As[(kq * 4 + 0) * 132 + r] = v.x;
            As[(kq * 4 + 1) * 132 + r] = v.y;
            As[(kq * 4 + 2) * 132 + r] = v.z;
            As[(kq * 4 + 3) * 132 + r] = v.w;
        }
        // Load B tile 64x16 (transposed into smem)
        {
            int L  = tid;                     // 0..255
            int n  = L >> 2;                  // 0..63
            int kq = L & 3;
            float4 v = *reinterpret_cast<const float4*>(
                &wih[(size_t)(n0 + n) * INF + k0 + kq * 4]);
            Bs[(kq * 4 + 0) * 68 + n] = v.x;
            Bs[(kq * 4 + 1) * 68 + n] = v.y;
            Bs[(kq * 4 + 2) * 68 + n] = v.z;
            Bs[(kq * 4 + 3) * 68 + n] = v.w;
        }
        __syncthreads();

        #pragma unroll
        for (int k = 0; k < 16; k++) {
            float4 a0 = *reinterpret_cast<const float4*>(&As[k * 132 + ty * 8]);
            float4 a1 = *reinterpret_cast<const float4*>(&As[k * 132 + ty * 8 + 4]);
            float4 bv = *reinterpret_cast<const float4*>(&Bs[k * 68 + tx * 4]);
            float a[8] = {a0.x, a0.y, a0.z, a0.w, a1.x, a1.y, a1.z, a1.w};
            float bb[4] = {bv.x, bv.y, bv.z, bv.w};
            #pragma unroll
            for (int i = 0; i < 8; i++)
                #pragma unroll
                for (int j = 0; j < 4; j++)
                    acc[i][j] = fmaf(a[i], bb[j], acc[i][j]);
        }
        __syncthreads();
    }

    #pragma unroll
    for (int i = 0; i < 8; i++) {
        int m = m0 + ty * 8 + i;
        #pragma unroll
        for (int j = 0; j < 4; j++) {
            int n = n0 + tx * 4 + j;
            gi[(size_t)m * G3 + n] = acc[i][j] + bih[n];
        }
    }
}

// =====================================================================
// Kernel 2: persistent GRU recurrence.
// 128 CTAs x 256 threads. CTA cb owns hidden columns j0=cb*4 .. j0+3
// (for all 3 gates). Thread t: b = t>>2, jj = t&3 -> owns cell (b, j0+jj),
// keeps h_prev(b,j) in a register across steps.
// Per step: gh = h @ W_hh^T for the 12 owned rows, K=512 staged through
// shared memory in 64-wide chunks; then gate math; then global barrier.
// =====================================================================
__global__ __launch_bounds__(256, 1) void gru_recur_kernel(
    const float* __restrict__ whh,
    const float* __restrict__ bhh,
    const float* __restrict__ gi,
    float* __restrict__ outs)   // may be nullptr
{
    __shared__ float w_sh[12 * 516];   // 12 weight rows, padded stride 516
    __shared__ float h_sh[64 * 68];    // 64 x 64 chunk of h, padded stride 68

    const int tid = threadIdx.x;
    const int cb  = blockIdx.x;
    const int j0  = cb * 4;
    const int b   = tid >> 2;          // 0..63
    const int jj  = tid & 3;           // 0..3
    const int j   = j0 + jj;

    // Load this CTA's 12 W_hh rows into shared (once).
    for (int idx = tid; idx < 12 * 512; idx += 256) {
        int row = idx >> 9;            // 0..11
        int k   = idx & 511;
        int g   = row >> 2;            // gate 0..2
        int jr  = row & 3;
        w_sh[(g * 4 + jr) * 516 + k] = whh[((size_t)g * HH + j0 + jr) * HH + k];
    }
    const float bh_r = bhh[j];
    const float bh_z = bhh[HH + j];
    const float bh_n = bhh[2 * HH + j];
    float hreg = 0.f;                  // h_prev(b,j) lives here
    __syncthreads();

    const float* wr   = &w_sh[(0 * 4 + jj) * 516];
    const float* wz   = &w_sh[(1 * 4 + jj) * 516];
    const float* wn   = &w_sh[(2 * 4 + jj) * 516];
    const float* hrow = &h_sh[b * 68];

    for (int t = 0; t < TT; t++) {
        const float* hcur = g_h + (t & 1) * BH;
        float*       hnxt = g_h + ((t + 1) & 1) * BH;

        float acc0 = bh_r, acc1 = bh_z, acc2 = bh_n;

        for (int kc = 0; kc < HH; kc += 64) {
            // Stage 64x64 chunk of h (bypass L1: other CTAs wrote it).
            #pragma unroll
            for (int it = 0; it < 4; it++) {
                int q   = tid + it * 256;      // 0..1023 float4 slots
                int row = q >> 4;
                int c4  = q & 15;
                float4 v = __ldcg(reinterpret_cast<const float4*>(
                    hcur + (size_t)row * HH + kc + c4 * 4));
                *reinterpret_cast<float4*>(&h_sh[row * 68 + c4 * 4]) = v;
            }
            __syncthreads();

            #pragma unroll
            for (int k4 = 0; k4 < 16; k4++) {
                float4 h4 = *reinterpret_cast<const float4*>(hrow + k4 * 4);
                float4 r4 = *reinterpret_cast<const float4*>(wr + kc + k4 * 4);
                float4 z4 = *reinterpret_cast<const float4*>(wz + kc + k4 * 4);
                float4 n4 = *reinterpret_cast<const float4*>(wn + kc + k4 * 4);
                acc0 = fmaf(h4.x, r4.x, acc0); acc0 = fmaf(h4.y, r4.y, acc0);
                acc0 = fmaf(h4.z, r4.z, acc0); acc0 = fmaf(h4.w, r4.w, acc0);
                acc1 = fmaf(h4.x, z4.x, acc1); acc1 = fmaf(h4.y, z4.y, acc1);
                acc1 = fmaf(h4.z, z4.z, acc1); acc1 = fmaf(h4.w, z4.w, acc1);
                acc2 = fmaf(h4.x, n4.x, acc2); acc2 = fmaf(h4.y, n4.y, acc2);
                acc2 = fmaf(h4.z, n4.z, acc2); acc2 = fmaf(h4.w, n4.w, acc2);
            }
            __syncthreads();
        }

        // Gate math (torch GRU order r, z, n)
        const float* gib = gi + (size_t)t * BH3 + (size_t)b * G3 + j;
        float gr = gib[0], gz = gib[HH], gn = gib[2 * HH];
        float r = 1.f / (1.f + __expf(-(gr + acc0)));
        float z = 1.f / (1.f + __expf(-(gz + acc1)));
        float n = tanhf(gn + r * acc2);
        float hnew = n + z * (hreg - n);   // (1-z)*n + z*h
        hreg = hnew;

        hnxt[(size_t)b * HH + j] = hnew;
        if (outs) outs[(size_t)t * BH + (size_t)b * HH + j] = hnew;

        // Grid barrier: make writes visible, arrive, spin until all arrived.
        __threadfence();
        __syncthreads();
        if (tid == 0) {
            atomicAdd(&g_bar, 1u);
            unsigned target = (unsigned)(t + 1) * NCTA;
            while (*(volatile unsigned*)&g_bar < target) { __nanosleep(64); }
            __threadfence();
        }
        __syncthreads();
    }
}

// =====================================================================
// Kernel 3: out[b,o] = h_final[b,:] . fc_w[o,:] + fc_b[o]
// =====================================================================
__global__ __launch_bounds__(256) void fc_kernel(
    const float* __restrict__ hsrc,    // final h, [B,H]
    const float* __restrict__ fcw,
    const float* __restrict__ fcb,
    float* __restrict__ out)
{
    __shared__ float hrow[HH];
    const int b = blockIdx.x;
    const int o = threadIdx.x;
    for (int i = threadIdx.x; i < HH; i += 256)
        hrow[i] = hsrc[(size_t)b * HH + i];
    __syncthreads();

    float acc = fcb[o];
    const float4* w4 = reinterpret_cast<const float4*>(fcw + (size_t)o * HH);
    #pragma unroll 8
    for (int k4 = 0; k4 < HH / 4; k4++) {
        float4 w = w4[k4];
        acc = fmaf(hrow[k4 * 4 + 0], w.x, acc);
        acc = fmaf(hrow[k4 * 4 + 1], w.y, acc);
        acc = fmaf(hrow[k4 * 4 + 2], w.z, acc);
        acc = fmaf(hrow[k4 * 4 + 3], w.w, acc);
    }
    out[(size_t)b * OUTF + o] = acc;
}

// Kernel 4: hn = final h ; h0 = zeros
__global__ void tail_kernel(const float* __restrict__ hsrc,
                            float* __restrict__ dst_hn,
                            float* __restrict__ dst_h0,
                            int write_hn, int write_h0)
{
    int i = blockIdx.x * blockDim.x + threadIdx.x;
    if (i < BH) {
        if (write_hn) dst_hn[i] = hsrc[i];
        if (write_h0) dst_h0[i] = 0.f;
    }
}

// =====================================================================
extern "C" void kernel_launch(void* const* d_in, const int* in_sizes, int n_in,
                              void* d_out, int out_size)
{
    const float* x   = (const float*)d_in[0];
    const float* wih = (const float*)d_in[1];
    const float* whh = (const float*)d_in[2];
    const float* bih = (const float*)d_in[3];
    const float* bhh = (const float*)d_in[4];
    const float* fcw = (const float*)d_in[5];
    const float* fcb = (const float*)d_in[6];
    float* out = (float*)d_out;

    void *p_h = nullptr, *p_bar = nullptr, *p_gi = nullptr;
    cudaGetSymbolAddress(&p_h,  g_h);
    cudaGetSymbolAddress(&p_bar, g_bar);
    cudaGetSymbolAddress(&p_gi, g_gi);

    // Reset recurrence state each invocation (capturable, deterministic).
    cudaMemsetAsync(p_h,  0, sizeof(float) * 2 * BH, 0);
    cudaMemsetAsync(p_bar, 0, sizeof(unsigned), 0);

    // Phase 1: input-side projections
    dim3 gg(G3 / 64, (TT * BB) / 128);   // (24, 512)
    gi_gemm_kernel<<<gg, 256>>>(x, wih, bih, (float*)p_gi);

    // Output layout: concatenation of (outs[T,B,H], out[B,OUT], hn[B,H], h0[B,H])
    const long long OUTS_N = (long long)TT * BH;   // 33,554,432
    long long remaining = (long long)out_size;
    float* outs_dst = nullptr;
    long long off = 0;
    if (remaining >= OUTS_N) { outs_dst = out; off = OUTS_N; }

    // Phase 2: recurrence (final h lands in g_h[0..BH) since T is even)
    gru_recur_kernel<<<NCTA, 256>>>(whh, bhh, (const float*)p_gi, outs_dst);

    const float* hfinal = (const float*)p_h;   // parity (T&1)==0 buffer

    // Phase 3: epilogue outputs
    if (remaining - off >= (long long)BB * OUTF) {
        fc_kernel<<<BB, 256>>>(hfinal, fcw, fcb, out + off);
        off += (long long)BB * OUTF;
    } else if (remaining == (long long)BB * OUTF) {
        // out_size holds only the fc output
        fc_kernel<<<BB, 256>>>(hfinal, fcw, fcb, out);
        off = remaining;
    }
    int wh = (remaining - off >= (long long)BH) ? 1 : 0;
    int w0 = (remaining - off >= (long long)2 * BH) ? 1 : 0;
    if (wh) {
        tail_kernel<<<(BH + 255) / 256, 256>>>(hfinal,
                                               out + off,
                                               out + off + BH,
                                               wh, w0);
    }
}

// round 4
// speedup vs baseline: 1.2595x; 1.2595x over previous
#include <cuda_runtime.h>
#include <math.h>

// Problem constants
#define TT   1024
#define BB   64
#define INF  256
#define HH   512
#define OUTF 256
#define G3   1536           // 3*H
#define BH   (BB*HH)        // 32768
#define BH3  (BB*G3)        // 98304
#define NCTA 128            // recurrence grid (<= 148 SMs -> co-resident)
#define HS   516            // padded row stride (floats) for h/w smem tiles

// ---------------- scratch (no allocations allowed) ----------------
__device__ float    g_gi[(size_t)TT * BH3];   // [T,B,3H] input-side gate projections
__device__ float    g_h[2 * BH];              // double-buffered hidden state
__device__ unsigned g_bar;                    // grid-barrier arrival counter

// ---------------- f32x2 helpers (FFMA2: full-rate fp32 on sm_10x) -----
__device__ __forceinline__ void fma2(unsigned long long& acc,
                                     unsigned long long a,
                                     unsigned long long b) {
    asm("fma.rn.f32x2 %0, %1, %2, %0;" : "+l"(acc) : "l"(a), "l"(b));
}
__device__ __forceinline__ float fold2(unsigned long long v) {
    float2 f = *reinterpret_cast<float2*>(&v);
    return f.x + f.y;
}
__device__ __forceinline__ unsigned long long dupf(float x) {
    unsigned long long r;
    asm("mov.b64 %0, {%1, %1};" : "=l"(r) : "r"(__float_as_uint(x)));
    return r;
}

// =====================================================================
// Kernel 1: gi[t,b,g] = sum_i x[b,t,i] * W_ih[g,i] + b_ih[g]
// GEMM: M = T*B (row m = t*64 + b), N = 1536, K = 256
// Tile: BM=128, BN=64, BK=16, 256 threads, 8x4 microtile via f32x2 pairs.
// =====================================================================
__global__ __launch_bounds__(256) void gi_gemm_kernel(
    const float* __restrict__ x,
    const float* __restrict__ wih,
    const float* __restrict__ bih,
    float* __restrict__ gi)
{
    __shared__ float As[16 * 132];   // [k][m], padded stride 132
    __shared__ float Bs[16 * 68];    // [k][n], padded stride 68

    const int tid = threadIdx.x;
    const int m0  = blockIdx.y * 128;
    const int n0  = blockIdx.x * 64;
    const int ty  = tid >> 4;        // 0..15 -> m rows ty*8..ty*8+7
    const int tx  = tid & 15;        // 0..15 -> n cols tx*4..tx*4+3

    unsigned long long acc[4][4];    // [m-pair][n], each packs rows (2i,2i+1)
    #pragma unroll
    for (int i = 0; i < 4; i++)
        #pragma unroll
        for (int j = 0; j < 4; j++) acc[i][j] = 0ULL;

    for (int k0 = 0; k0 < INF; k0 += 16) {
        // Load A tile 128x16 (transposed). Row m -> x row (b*T + t).
        #pragma unroll
        for (int it = 0; it < 2; it++) {
            int L  = tid + it * 256;          // float4 slots
            int r  = L >> 2;                  // 0..127
            int kq = L & 3;
            int m  = m0 + r;
            int t  = m >> 6;
            int b  = m & 63;
            float4 v = *reinterpret_cast<const float4*>(
                &x[((size_t)b * TT + t) * INF + k0 + kq * 4]);
            As[(kq * 4 + 0) * 132 + r] = v.x;
            As[(kq * 4 + 1) * 132 + r] = v.y;
            As[(kq * 4 + 2) * 132 + r] = v.z;
            As[(kq * 4 + 3) * 132 + r] = v.w;
        }
        // Load B tile 64x16 (transposed)
        {
            int L  = tid;
            int n  = L >> 2;
            int kq = L & 3;
            float4 v = *reinterpret_cast<const float4*>(
                &wih[(size_t)(n0 + n) * INF + k0 + kq * 4]);
            Bs[(kq * 4 + 0) * 68 + n] = v.x;
            Bs[(kq * 4 + 1) * 68 + n] = v.y;
            Bs[(kq * 4 + 2) * 68 + n] = v.z;
            Bs[(kq * 4 + 3) * 68 + n] = v.w;
        }
        __syncthreads();

        #pragma unroll
        for (int k = 0; k < 16; k++) {
            const ulonglong2* ap =
                reinterpret_cast<const ulonglong2*>(&As[k * 132 + ty * 8]);
            ulonglong2 a01 = ap[0];   // packs (a0,a1),(a2,a3)
            ulonglong2 a23 = ap[1];   // packs (a4,a5),(a6,a7)
            float4 bv = *reinterpret_cast<const float4*>(&Bs[k * 68 + tx * 4]);
            unsigned long long bd[4] = {dupf(bv.x), dupf(bv.y), dupf(bv.z), dupf(bv.w)};
            unsigned long long ap4[4] = {a01.x, a01.y, a23.x, a23.y};
            #pragma unroll
            for (int i = 0; i < 4; i++)
                #pragma unroll
                for (int j = 0; j < 4; j++)
                    fma2(acc[i][j], ap4[i], bd[j]);
        }
        __syncthreads();
    }

    #pragma unroll
    for (int i = 0; i < 4; i++) {
        int mA = m0 + ty * 8 + 2 * i;
        #pragma unroll
        for (int j = 0; j < 4; j++) {
            int n = n0 + tx * 4 + j;
            float2 v = *reinterpret_cast<float2*>(&acc[i][j]);
            float bb = bih[n];
            gi[(size_t)mA * G3 + n]       = v.x + bb;
            gi[(size_t)(mA + 1) * G3 + n] = v.y + bb;
        }
    }
}

// =====================================================================
// Kernel 2: persistent GRU recurrence.
// 128 CTAs x 256 threads. CTA cb owns hidden columns j0=cb*4 .. j0+3
// (all 3 gates). Thread t: b = t>>2, jj = t&3 -> owns cell (b, j0+jj),
// keeps h_prev(b,j) in a register across all 1024 steps.
// Per step: full 64x512 h staged via cp.async in 4 pipelined chunks,
// f32x2 dot products, gate math, global grid barrier.
// Dynamic smem: w (12x516) + h (64x516) = 156,864 B -> 1 CTA/SM.
// =====================================================================
__global__ __launch_bounds__(256, 1) void gru_recur_kernel(
    const float* __restrict__ whh,
    const float* __restrict__ bhh,
    const float* __restrict__ gi,
    float* __restrict__ outs)   // may be nullptr
{
    extern __shared__ float smem[];
    float* w_sh = smem;             // 12 * HS
    float* h_sh = smem + 12 * HS;   // 64 * HS

    const int tid = threadIdx.x;
    const int cb  = blockIdx.x;
    const int j0  = cb * 4;
    const int b   = tid >> 2;          // 0..63
    const int jj  = tid & 3;           // 0..3
    const int j   = j0 + jj;

    // Load this CTA's 12 W_hh rows into shared (once, resident all steps).
    for (int idx = tid; idx < 12 * HH; idx += 256) {
        int row = idx >> 9;            // 0..11 (gate*4 + jr)
        int k   = idx & 511;
        int g   = row >> 2;
        int jr  = row & 3;
        w_sh[row * HS + k] = whh[((size_t)g * HH + j0 + jr) * HH + k];
    }
    const float bh_r = bhh[j];
    const float bh_z = bhh[HH + j];
    const float bh_n = bhh[2 * HH + j];
    float hreg = 0.f;
    __syncthreads();

    const ulonglong2* wr2 = reinterpret_cast<const ulonglong2*>(w_sh + (0 + jj) * HS);
    const ulonglong2* wz2 = reinterpret_cast<const ulonglong2*>(w_sh + (4 + jj) * HS);
    const ulonglong2* wn2 = reinterpret_cast<const ulonglong2*>(w_sh + (8 + jj) * HS);
    const ulonglong2* h2  = reinterpret_cast<const ulonglong2*>(h_sh + b * HS);

    // Prefetch gi for t=0 (hidden under first staging)
    float g_r, g_z, g_n;
    {
        const float* gib = gi + (size_t)b * G3 + j;
        g_r = __ldg(gib); g_z = __ldg(gib + HH); g_n = __ldg(gib + 2 * HH);
    }

    for (int t = 0; t < TT; t++) {
        const float* hcur = g_h + (t & 1) * BH;
        float*       hnxt = g_h + ((t + 1) & 1) * BH;

        // Stage full h (64x512) in 4 chunks of 128 cols via cp.async.cg
        #pragma unroll
        for (int c = 0; c < 4; c++) {
            #pragma unroll
            for (int it = 0; it < 8; it++) {
                int s   = tid + it * 256;      // 0..2047 float4 slots
                int row = s >> 5;              // 0..63
                int c4  = s & 31;              // 0..31
                const float* gp = hcur + (size_t)row * HH + c * 128 + c4 * 4;
                unsigned sa = (unsigned)__cvta_generic_to_shared(
                    h_sh + row * HS + c * 128 + c4 * 4);
                asm volatile("cp.async.cg.shared.global [%0], [%1], 16;\n"
                             :: "r"(sa), "l"(gp));
            }
            asm volatile("cp.async.commit_group;\n");
        }

        unsigned long long ar0 = 0, ar1 = 0, az0 = 0, az1 = 0, an0 = 0, an1 = 0;

        #define GRU_CHUNK(c)                                                   \
        {                                                                      \
            _Pragma("unroll")                                                  \
            for (int kk = 0; kk < 32; kk++) {                                  \
                ulonglong2 hv = h2[(c) * 32 + kk];                             \
                ulonglong2 rv = wr2[(c) * 32 + kk];                            \
                ulonglong2 zv = wz2[(c) * 32 + kk];                            \
                ulonglong2 nv = wn2[(c) * 32 + kk];                            \
                fma2(ar0, hv.x, rv.x); fma2(ar1, hv.y, rv.y);                  \
                fma2(az0, hv.x, zv.x); fma2(az1, hv.y, zv.y);                  \
                fma2(an0, hv.x, nv.x); fma2(an1, hv.y, nv.y);                  \
            }                                                                  \
        }

        asm volatile("cp.async.wait_group 3;\n" ::: "memory");
        __syncthreads();
        GRU_CHUNK(0);
        asm volatile("cp.async.wait_group 2;\n" ::: "memory");
        __syncthreads();
        GRU_CHUNK(1);
        asm volatile("cp.async.wait_group 1;\n" ::: "memory");
        __syncthreads();
        GRU_CHUNK(2);
        asm volatile("cp.async.wait_group 0;\n" ::: "memory");
        __syncthreads();
        GRU_CHUNK(3);
        #undef GRU_CHUNK

        // Gate math (torch GRU order r, z, n). bias_hh_n inside r-mul.
        float hr = fold2(ar0) + fold2(ar1);
        float hz = fold2(az0) + fold2(az1);
        float hn = fold2(an0) + fold2(an1);
        float rr = 1.f / (1.f + __expf(-(g_r + bh_r + hr)));
        float zz = 1.f / (1.f + __expf(-(g_z + bh_z + hz)));
        float nn = tanhf(g_n + rr * (hn + bh_n));
        float hnew = nn + zz * (hreg - nn);    // (1-z)*n + z*h
        hreg = hnew;

        hnxt[(size_t)b * HH + j] = hnew;
        if (outs) outs[(size_t)t * BH + (size_t)b * HH + j] = hnew;

        // Prefetch next step's gi BEFORE the barrier (latency hidden by wait)
        {
            int tn = (t + 1 < TT) ? (t + 1) : t;
            const float* gib = gi + (size_t)tn * BH3 + (size_t)b * G3 + j;
            g_r = __ldg(gib); g_z = __ldg(gib + HH); g_n = __ldg(gib + 2 * HH);
        }

        // Grid barrier
        __threadfence();
        __syncthreads();
        if (tid == 0) {
            atomicAdd(&g_bar, 1u);
            unsigned target = (unsigned)(t + 1) * NCTA;
            while (*(volatile unsigned*)&g_bar < target) { __nanosleep(64); }
            __threadfence();
        }
        __syncthreads();
    }
}

// =====================================================================
// Kernel 3: out[b,o] = h_final[b,:] . fc_w[o,:] + fc_b[o]
// =====================================================================
__global__ __launch_bounds__(256) void fc_kernel(
    const float* __restrict__ hsrc,
    const float* __restrict__ fcw,
    const float* __restrict__ fcb,
    float* __restrict__ out)
{
    __shared__ float hrow[HH];
    const int b = blockIdx.x;
    const int o = threadIdx.x;
    for (int i = threadIdx.x; i < HH; i += 256)
        hrow[i] = hsrc[(size_t)b * HH + i];
    __syncthreads();

    float acc = fcb[o];
    const float4* w4 = reinterpret_cast<const float4*>(fcw + (size_t)o * HH);
    #pragma unroll 8
    for (int k4 = 0; k4 < HH / 4; k4++) {
        float4 w = w4[k4];
        acc = fmaf(hrow[k4 * 4 + 0], w.x, acc);
        acc = fmaf(hrow[k4 * 4 + 1], w.y, acc);
        acc = fmaf(hrow[k4 * 4 + 2], w.z, acc);
        acc = fmaf(hrow[k4 * 4 + 3], w.w, acc);
    }
    out[(size_t)b * OUTF + o] = acc;
}

// Kernel 4: hn = final h ; h0 = zeros
__global__ void tail_kernel(const float* __restrict__ hsrc,
                            float* __restrict__ dst_hn,
                            float* __restrict__ dst_h0,
                            int write_hn, int write_h0)
{
    int i = blockIdx.x * blockDim.x + threadIdx.x;
    if (i < BH) {
        if (write_hn) dst_hn[i] = hsrc[i];
        if (write_h0) dst_h0[i] = 0.f;
    }
}

// =====================================================================
extern "C" void kernel_launch(void* const* d_in, const int* in_sizes, int n_in,
                              void* d_out, int out_size)
{
    const float* x   = (const float*)d_in[0];
    const float* wih = (const float*)d_in[1];
    const float* whh = (const float*)d_in[2];
    const float* bih = (const float*)d_in[3];
    const float* bhh = (const float*)d_in[4];
    const float* fcw = (const float*)d_in[5];
    const float* fcb = (const float*)d_in[6];
    float* out = (float*)d_out;

    void *p_h = nullptr, *p_bar = nullptr, *p_gi = nullptr;
    cudaGetSymbolAddress(&p_h,  g_h);
    cudaGetSymbolAddress(&p_bar, g_bar);
    cudaGetSymbolAddress(&p_gi, g_gi);

    const int RECUR_SMEM = (12 + 64) * HS * (int)sizeof(float);   // 156,864 B
    cudaFuncSetAttribute(gru_recur_kernel,
                         cudaFuncAttributeMaxDynamicSharedMemorySize, RECUR_SMEM);

    // Reset recurrence state each invocation (capturable, deterministic).
    cudaMemsetAsync(p_h,  0, sizeof(float) * 2 * BH, 0);
    cudaMemsetAsync(p_bar, 0, sizeof(unsigned), 0);

    // Phase 1: input-side projections
    dim3 gg(G3 / 64, (TT * BB) / 128);   // (24, 512)
    gi_gemm_kernel<<<gg, 256>>>(x, wih, bih, (float*)p_gi);

    // Output layout: concatenation of (outs[T,B,H], out[B,OUT], hn[B,H], h0[B,H])
    const long long OUTS_N = (long long)TT * BH;
    long long remaining = (long long)out_size;
    float* outs_dst = nullptr;
    long long off = 0;
    if (remaining >= OUTS_N) { outs_dst = out; off = OUTS_N; }

    // Phase 2: recurrence (final h lands in g_h[0..BH) since T is even)
    gru_recur_kernel<<<NCTA, 256, RECUR_SMEM>>>(whh, bhh, (const float*)p_gi, outs_dst);

    const float* hfinal = (const float*)p_h;

    // Phase 3: epilogue outputs
    if (remaining - off >= (long long)BB * OUTF) {
        fc_kernel<<<BB, 256>>>(hfinal, fcw, fcb, out + off);
        off += (long long)BB * OUTF;
    } else if (remaining == (long long)BB * OUTF) {
        fc_kernel<<<BB, 256>>>(hfinal, fcw, fcb, out);
        off = remaining;
    }
    int wh = (remaining - off >= (long long)BH) ? 1 : 0;
    int w0 = (remaining - off >= (long long)2 * BH) ? 1 : 0;
    if (wh) {
        tail_kernel<<<(BH + 255) / 256, 256>>>(hfinal,
                                               out + off,
                                               out + off + BH,
                                               wh, w0);
    }
}

// round 5
// speedup vs baseline: 1.3996x; 1.1113x over previous
#include <cuda_runtime.h>
#include <math.h>

// Problem constants
#define TT   1024
#define BB   64
#define INF  256
#define HH   512
#define OUTF 256
#define G3   1536           // 3*H
#define BH   (BB*HH)        // 32768
#define BH3  (BB*G3)        // 98304
#define NCTA 128            // recurrence grid (<= 148 SMs -> all co-resident)
#define WPAD 520            // padded row stride (floats) for weight smem

// ---------------- scratch (no allocations allowed) ----------------
__device__ float    g_gi[(size_t)TT * BH3];   // [T,B,3H] input-side gate projections
__device__ float    g_h[2 * BH];              // double-buffered hidden state
__device__ unsigned g_bar;                    // grid-barrier arrival counter

// ---------------- f32x2 helpers (FFMA2: full-rate fp32 on sm_10x) -----
__device__ __forceinline__ void fma2(unsigned long long& acc,
                                     unsigned long long a,
                                     unsigned long long b) {
    asm("fma.rn.f32x2 %0, %1, %2, %0;" : "+l"(acc) : "l"(a), "l"(b));
}
__device__ __forceinline__ unsigned long long dupf(float x) {
    unsigned long long r;
    asm("mov.b64 %0, {%1, %1};" : "=l"(r) : "r"(__float_as_uint(x)));
    return r;
}

// =====================================================================
// Kernel 1: gi[t,b,g] = sum_i x[b,t,i] * W_ih[g,i] + b_ih[g]
// GEMM: M = T*B (row m = t*64 + b), N = 1536, K = 256
// Tile: BM=128, BN=64, BK=16, 256 threads, 8x4 microtile via f32x2 pairs.
// =====================================================================
__global__ __launch_bounds__(256) void gi_gemm_kernel(
    const float* __restrict__ x,
    const float* __restrict__ wih,
    const float* __restrict__ bih,
    float* __restrict__ gi)
{
    __shared__ float As[16 * 132];   // [k][m], padded stride 132
    __shared__ float Bs[16 * 68];    // [k][n], padded stride 68

    const int tid = threadIdx.x;
    const int m0  = blockIdx.y * 128;
    const int n0  = blockIdx.x * 64;
    const int ty  = tid >> 4;        // 0..15 -> m rows ty*8..ty*8+7
    const int tx  = tid & 15;        // 0..15 -> n cols tx*4..tx*4+3

    unsigned long long acc[4][4];    // [m-pair][n]
    #pragma unroll
    for (int i = 0; i < 4; i++)
        #pragma unroll
        for (int j = 0; j < 4; j++) acc[i][j] = 0ULL;

    for (int k0 = 0; k0 < INF; k0 += 16) {
        #pragma unroll
        for (int it = 0; it < 2; it++) {
            int L  = tid + it * 256;
            int r  = L >> 2;
            int kq = L & 3;
            int m  = m0 + r;
            int t  = m >> 6;
            int b  = m & 63;
            float4 v = *reinterpret_cast<const float4*>(
                &x[((size_t)b * TT + t) * INF + k0 + kq * 4]);
            As[(kq * 4 + 0) * 132 + r] = v.x;
            As[(kq * 4 + 1) * 132 + r] = v.y;
            As[(kq * 4 + 2) * 132 + r] = v.z;
            As[(kq * 4 + 3) * 132 + r] = v.w;
        }
        {
            int L  = tid;
            int n  = L >> 2;
            int kq = L & 3;
            float4 v = *reinterpret_cast<const float4*>(
                &wih[(size_t)(n0 + n) * INF + k0 + kq * 4]);
            Bs[(kq * 4 + 0) * 68 + n] = v.x;
            Bs[(kq * 4 + 1) * 68 + n] = v.y;
            Bs[(kq * 4 + 2) * 68 + n] = v.z;
            Bs[(kq * 4 + 3) * 68 + n] = v.w;
        }
        __syncthreads();

        #pragma unroll
        for (int k = 0; k < 16; k++) {
            const ulonglong2* ap =
                reinterpret_cast<const ulonglong2*>(&As[k * 132 + ty * 8]);
            ulonglong2 a01 = ap[0];
            ulonglong2 a23 = ap[1];
            float4 bv = *reinterpret_cast<const float4*>(&Bs[k * 68 + tx * 4]);
            unsigned long long bd[4] = {dupf(bv.x), dupf(bv.y), dupf(bv.z), dupf(bv.w)};
            unsigned long long ap4[4] = {a01.x, a01.y, a23.x, a23.y};
            #pragma unroll
            for (int i = 0; i < 4; i++)
                #pragma unroll
                for (int j = 0; j < 4; j++)
                    fma2(acc[i][j], ap4[i], bd[j]);
        }
        __syncthreads();
    }

    #pragma unroll
    for (int i = 0; i < 4; i++) {
        int mA = m0 + ty * 8 + 2 * i;
        #pragma unroll
        for (int j = 0; j < 4; j++) {
            int n = n0 + tx * 4 + j;
            float2 v = *reinterpret_cast<float2*>(&acc[i][j]);
            float bb = bih[n];
            gi[(size_t)mA * G3 + n]       = v.x + bb;
            gi[(size_t)(mA + 1) * G3 + n] = v.y + bb;
        }
    }
}

// =====================================================================
// Kernel 2: persistent GRU recurrence. 128 CTAs x 256 threads.
// CTA cb owns hidden columns j0=cb*4..j0+3 (all 3 gates).
// Thread t: b = t>>2, q = t&3. Lane q covers k in {16m + 4q .. 16m+4q+3}
// (a strided quarter of K) -> h LDGs from the 4 lanes of a b-group are
// 64B-contiguous (coalesced), no SMEM staging of h at all.
// Weights live in SMEM (read as 64B broadcast wavefronts, 1 cyc each).
// Partial gate sums reduced across the 4 q-lanes by butterfly shuffle;
// lane q finishes cell (b, j0+q). Grid barrier per step.
// =====================================================================
__global__ __launch_bounds__(256, 1) void gru_recur_kernel(
    const float* __restrict__ whh,
    const float* __restrict__ bhh,
    const float* __restrict__ gi,
    float* __restrict__ outs)   // may be nullptr
{
    __shared__ float w_sh[12 * WPAD];   // 12 weight rows (g*4+jr), ~25 KB

    const int tid = threadIdx.x;
    const int cb  = blockIdx.x;
    const int j0  = cb * 4;
    const int b   = tid >> 2;          // 0..63
    const int q   = tid & 3;           // 0..3 (k-phase AND owned j-offset)
    const int j   = j0 + q;

    // Load this CTA's 12 W_hh rows into shared (once, resident all steps).
    for (int idx = tid; idx < 12 * 512; idx += 256) {
        int row = idx >> 9;            // 0..11
        int k   = idx & 511;
        int g   = row >> 2;
        int jr  = row & 3;
        w_sh[row * WPAD + k] = whh[((size_t)g * HH + j0 + jr) * HH + k];
    }
    const float bh_r = bhh[j];
    const float bh_z = bhh[HH + j];
    const float bh_n = bhh[2 * HH + j];
    float hreg = 0.f;                  // h_prev(b,j) lives here
    __syncthreads();

    // Prefetch gi for t=0
    float g_r, g_z, g_n;
    {
        const float* gib = gi + (size_t)b * G3 + j;
        g_r = __ldg(gib); g_z = __ldg(gib + HH); g_n = __ldg(gib + 2 * HH);
    }

    for (int t = 0; t < TT; t++) {
        const float* hb   = g_h + (t & 1) * BH + (size_t)b * HH;
        float*       hnxt = g_h + ((t + 1) & 1) * BH;

        unsigned long long acc[12];
        #pragma unroll
        for (int r = 0; r < 12; r++) acc[r] = 0ULL;

        // h streamed from L2 in 4 chunks of 128 k (8 float4/thread),
        // double-buffered in registers.
        float4 buf[2][8];
        #pragma unroll
        for (int i = 0; i < 8; i++)
            buf[0][i] = __ldcg(reinterpret_cast<const float4*>(
                hb + i * 16 + q * 4));

        #pragma unroll
        for (int c = 0; c < 4; c++) {
            const int cur = c & 1;
            if (c < 3) {
                #pragma unroll
                for (int i = 0; i < 8; i++)
                    buf[cur ^ 1][i] = __ldcg(reinterpret_cast<const float4*>(
                        hb + (c + 1) * 128 + i * 16 + q * 4));
            }
            #pragma unroll
            for (int i = 0; i < 8; i++) {
                ulonglong2 h2 = *reinterpret_cast<ulonglong2*>(&buf[cur][i]);
                const int kb = c * 128 + i * 16 + q * 4;
                #pragma unroll
                for (int r = 0; r < 12; r++) {
                    ulonglong2 w2 = *reinterpret_cast<const ulonglong2*>(
                        &w_sh[r * WPAD + kb]);
                    fma2(acc[r], h2.x, w2.x);
                    fma2(acc[r], h2.y, w2.y);
                }
            }
        }

        // Fold f32x2 halves, then butterfly-reduce across the 4 q-lanes.
        float s[12];
        #pragma unroll
        for (int r = 0; r < 12; r++) {
            float2 f = *reinterpret_cast<float2*>(&acc[r]);
            s[r] = f.x + f.y;
        }
        #pragma unroll
        for (int d = 1; d <= 2; d <<= 1) {
            #pragma unroll
            for (int r = 0; r < 12; r++)
                s[r] += __shfl_xor_sync(0xffffffffu, s[r], d);
        }
        float hr = s[q], hz = s[4 + q], hn = s[8 + q];

        // Gate math (torch GRU order r, z, n)
        float rr = 1.f / (1.f + __expf(-(g_r + bh_r + hr)));
        float zz = 1.f / (1.f + __expf(-(g_z + bh_z + hz)));
        float nn = tanhf(g_n + rr * (hn + bh_n));
        float hnew = nn + zz * (hreg - nn);    // (1-z)*n + z*h
        hreg = hnew;

        hnxt[(size_t)b * HH + j] = hnew;
        if (outs) outs[(size_t)t * BH + (size_t)b * HH + j] = hnew;

        // Prefetch next step's gi BEFORE the barrier (latency hidden)
        {
            int tn = (t + 1 < TT) ? (t + 1) : t;
            const float* gib = gi + (size_t)tn * BH3 + (size_t)b * G3 + j;
            g_r = __ldg(gib); g_z = __ldg(gib + HH); g_n = __ldg(gib + 2 * HH);
        }

        // Grid barrier
        __threadfence();
        __syncthreads();
        if (tid == 0) {
            atomicAdd(&g_bar, 1u);
            const unsigned target = (unsigned)(t + 1) * NCTA;
            while (*(volatile unsigned*)&g_bar < target) { }
            __threadfence();
        }
        __syncthreads();
    }
}

// =====================================================================
// Kernel 3: out[b,o] = h_final[b,:] . fc_w[o,:] + fc_b[o]
// =====================================================================
__global__ __launch_bounds__(256) void fc_kernel(
    const float* __restrict__ hsrc,
    const float* __restrict__ fcw,
    const float* __restrict__ fcb,
    float* __restrict__ out)
{
    __shared__ float hrow[HH];
    const int b = blockIdx.x;
    const int o = threadIdx.x;
    for (int i = threadIdx.x; i < HH; i += 256)
        hrow[i] = hsrc[(size_t)b * HH + i];
    __syncthreads();

    float acc = fcb[o];
    const float4* w4 = reinterpret_cast<const float4*>(fcw + (size_t)o * HH);
    #pragma unroll 8
    for (int k4 = 0; k4 < HH / 4; k4++) {
        float4 w = w4[k4];
        acc = fmaf(hrow[k4 * 4 + 0], w.x, acc);
        acc = fmaf(hrow[k4 * 4 + 1], w.y, acc);
        acc = fmaf(hrow[k4 * 4 + 2], w.z, acc);
        acc = fmaf(hrow[k4 * 4 + 3], w.w, acc);
    }
    out[(size_t)b * OUTF + o] = acc;
}

// Kernel 4: hn = final h ; h0 = zeros
__global__ void tail_kernel(const float* __restrict__ hsrc,
                            float* __restrict__ dst_hn,
                            float* __restrict__ dst_h0,
                            int write_hn, int write_h0)
{
    int i = blockIdx.x * blockDim.x + threadIdx.x;
    if (i < BH) {
        if (write_hn) dst_hn[i] = hsrc[i];
        if (write_h0) dst_h0[i] = 0.f;
    }
}

// Profiling positioner: two no-op launches so ncu's "-s 5 -c 1" lands on
// gru_recur_kernel (launch order: memset, memset, dummy, dummy, gi, recur).
__global__ void dummy_kernel() {}

// =====================================================================
extern "C" void kernel_launch(void* const* d_in, const int* in_sizes, int n_in,
                              void* d_out, int out_size)
{
    const float* x   = (const float*)d_in[0];
    const float* wih = (const float*)d_in[1];
    const float* whh = (const float*)d_in[2];
    const float* bih = (const float*)d_in[3];
    const float* bhh = (const float*)d_in[4];
    const float* fcw = (const float*)d_in[5];
    const float* fcb = (const float*)d_in[6];
    float* out = (float*)d_out;

    void *p_h = nullptr, *p_bar = nullptr, *p_gi = nullptr;
    cudaGetSymbolAddress(&p_h,  g_h);
    cudaGetSymbolAddress(&p_bar, g_bar);
    cudaGetSymbolAddress(&p_gi, g_gi);

    // Reset recurrence state each invocation (capturable, deterministic).
    cudaMemsetAsync(p_h,  0, sizeof(float) * 2 * BH, 0);
    cudaMemsetAsync(p_bar, 0, sizeof(unsigned), 0);

    dummy_kernel<<<1, 32>>>();
    dummy_kernel<<<1, 32>>>();

    // Phase 1: input-side projections
    dim3 gg(G3 / 64, (TT * BB) / 128);   // (24, 512)
    gi_gemm_kernel<<<gg, 256>>>(x, wih, bih, (float*)p_gi);

    // Output layout: concatenation of (outs[T,B,H], out[B,OUT], hn[B,H], h0[B,H])
    const long long OUTS_N = (long long)TT * BH;
    long long remaining = (long long)out_size;
    float* outs_dst = nullptr;
    long long off = 0;
    if (remaining >= OUTS_N) { outs_dst = out; off = OUTS_N; }

    // Phase 2: recurrence (final h lands in g_h[0..BH) since T is even)
    gru_recur_kernel<<<NCTA, 256>>>(whh, bhh, (const float*)p_gi, outs_dst);

    const float* hfinal = (const float*)p_h;

    // Phase 3: epilogue outputs
    if (remaining - off >= (long long)BB * OUTF) {
        fc_kernel<<<BB, 256>>>(hfinal, fcw, fcb, out + off);
        off += (long long)BB * OUTF;
    } else if (remaining == (long long)BB * OUTF) {
        fc_kernel<<<BB, 256>>>(hfinal, fcw, fcb, out);
        off = remaining;
    }
    int wh = (remaining - off >= (long long)BH) ? 1 : 0;
    int w0 = (remaining - off >= (long long)2 * BH) ? 1 : 0;
    if (wh) {
        tail_kernel<<<(BH + 255) / 256, 256>>>(hfinal,
                                               out + off,
                                               out + off + BH,
                                               wh, w0);
    }
}

// round 7
// speedup vs baseline: 2.1841x; 1.5605x over previous
#include <cuda_runtime.h>
#include <math.h>

// Problem constants
#define TT   1024
#define BB   64
#define INF  256
#define HH   512
#define OUTF 256
#define G3   1536           // 3*H
#define BH   (BB*HH)        // 32768
#define BH3  (BB*G3)        // 98304
#define NCTA 128            // recurrence grid (<= 148 SMs -> all co-resident)
#define WPAD 520            // padded row stride (floats) for weight smem

// ---------------- scratch (no allocations allowed) ----------------
__device__ float    g_gi[(size_t)TT * BH3];   // [T,B,3H] input-side gate projections
__device__ float    g_h[2 * BH];              // double-buffered hidden state
__device__ unsigned g_bar;                    // grid-barrier arrival counter

// ---------------- f32x2 helpers (FFMA2: full-rate fp32 on sm_10x) -----
__device__ __forceinline__ void fma2(unsigned long long& acc,
                                     unsigned long long a,
                                     unsigned long long b) {
    asm("fma.rn.f32x2 %0, %1, %2, %0;" : "+l"(acc) : "l"(a), "l"(b));
}
__device__ __forceinline__ unsigned long long dupf(float x) {
    unsigned long long r;
    asm("mov.b64 %0, {%1, %1};" : "=l"(r) : "r"(__float_as_uint(x)));
    return r;
}

// =====================================================================
// Kernel 1: gi[t,b,g] = sum_i x[b,t,i] * W_ih[g,i] + b_ih[g]
// GEMM: M = T*B (row m = t*64 + b), N = 1536, K = 256
// =====================================================================
__global__ __launch_bounds__(256) void gi_gemm_kernel(
    const float* __restrict__ x,
    const float* __restrict__ wih,
    const float* __restrict__ bih,
    float* __restrict__ gi)
{
    __shared__ float As[16 * 132];   // [k][m]
    __shared__ float Bs[16 * 68];    // [k][n]

    const int tid = threadIdx.x;
    const int m0  = blockIdx.y * 128;
    const int n0  = blockIdx.x * 64;
    const int ty  = tid >> 4;
    const int tx  = tid & 15;

    unsigned long long acc[4][4];
    #pragma unroll
    for (int i = 0; i < 4; i++)
        #pragma unroll
        for (int j = 0; j < 4; j++) acc[i][j] = 0ULL;

    for (int k0 = 0; k0 < INF; k0 += 16) {
        #pragma unroll
        for (int it = 0; it < 2; it++) {
            int L  = tid + it * 256;
            int r  = L >> 2;
            int kq = L & 3;
            int m  = m0 + r;
            int t  = m >> 6;
            int b  = m & 63;
            float4 v = *reinterpret_cast<const float4*>(
                &x[((size_t)b * TT + t) * INF + k0 + kq * 4]);
            As[(kq * 4 + 0) * 132 + r] = v.x;
            As[(kq * 4 + 1) * 132 + r] = v.y;
            As[(kq * 4 + 2) * 132 + r] = v.z;
            As[(kq * 4 + 3) * 132 + r] = v.w;
        }
        {
            int n  = tid >> 2;
            int kq = tid & 3;
            float4 v = *reinterpret_cast<const float4*>(
                &wih[(size_t)(n0 + n) * INF + k0 + kq * 4]);
            Bs[(kq * 4 + 0) * 68 + n] = v.x;
            Bs[(kq * 4 + 1) * 68 + n] = v.y;
            Bs[(kq * 4 + 2) * 68 + n] = v.z;
            Bs[(kq * 4 + 3) * 68 + n] = v.w;
        }
        __syncthreads();

        #pragma unroll
        for (int k = 0; k < 16; k++) {
            const ulonglong2* ap =
                reinterpret_cast<const ulonglong2*>(&As[k * 132 + ty * 8]);
            ulonglong2 a01 = ap[0];
            ulonglong2 a23 = ap[1];
            float4 bv = *reinterpret_cast<const float4*>(&Bs[k * 68 + tx * 4]);
            unsigned long long bd[4] = {dupf(bv.x), dupf(bv.y), dupf(bv.z), dupf(bv.w)};
            unsigned long long ap4[4] = {a01.x, a01.y, a23.x, a23.y};
            #pragma unroll
            for (int i = 0; i < 4; i++)
                #pragma unroll
                for (int j = 0; j < 4; j++)
                    fma2(acc[i][j], ap4[i], bd[j]);
        }
        __syncthreads();
    }

    #pragma unroll
    for (int i = 0; i < 4; i++) {
        int mA = m0 + ty * 8 + 2 * i;
        #pragma unroll
        for (int j = 0; j < 4; j++) {
            int n = n0 + tx * 4 + j;
            float2 v = *reinterpret_cast<float2*>(&acc[i][j]);
            float bb = bih[n];
            gi[(size_t)mA * G3 + n]       = v.x + bb;
            gi[(size_t)(mA + 1) * G3 + n] = v.y + bb;
        }
    }
}

// =====================================================================
// Kernel 2: persistent GRU recurrence. 128 CTAs x 256 threads.
// CTA cb owns hidden columns j0=cb*4..j0+3 (all 3 gates = 12 W rows).
// Thread t: q = t&7 (k-phase), bp = t>>3 (0..31). Thread processes TWO
// batches {bp, bp+32} over k-slice {xi*32 + 4q + 0..3 : xi=0..15}:
//  - each weight LDS.128 (q-distinct 16B, 4-way bp broadcast = one 128B
//    wavefront) feeds 4 fma2.
//  - h LDG.128: 8 q-lanes x 16B contiguous = full 128B lines.
// Butterfly over the 8 q-lanes reduces 24 partials; lane (q&3, q>>2)
// owns cell (bp + 32*(q>>2), j0 + (q&3)). Grid barrier: release-atomic
// arrive + acquire poll (no __threadfence -> no CCTL.IVALL L1 flush).
// gi for step t+1 is prefetched into SEPARATE registers before the
// reduction and committed only after the gate math (R5 bug fix).
// =====================================================================
__global__ __launch_bounds__(256, 1) void gru_recur_kernel(
    const float* __restrict__ whh,
    const float* __restrict__ bhh,
    const float* __restrict__ gi,
    float* __restrict__ outs)   // may be nullptr
{
    __shared__ float w_sh[12 * WPAD];   // ~25 KB

    const int tid = threadIdx.x;
    const int cb  = blockIdx.x;
    const int j0  = cb * 4;
    const int q   = tid & 7;           // k-phase 0..7
    const int bp  = tid >> 3;          // 0..31 -> batches {bp, bp+32}
    const int jj  = q & 3;             // owned column offset
    const int wb  = q >> 2;            // owned batch selector
    const int bown = bp + (wb << 5);
    const int j    = j0 + jj;

    // Load this CTA's 12 W_hh rows into shared (once).
    for (int idx = tid; idx < 12 * 512; idx += 256) {
        int row = idx >> 9;            // 0..11  (gate*4 + jr)
        int k   = idx & 511;
        int g   = row >> 2;
        int jr  = row & 3;
        w_sh[row * WPAD + k] = whh[((size_t)g * HH + j0 + jr) * HH + k];
    }
    const float bh_r = bhh[j];
    const float bh_z = bhh[HH + j];
    const float bh_n = bhh[2 * HH + j];
    float hreg = 0.f;                  // h_prev(bown, j) lives here
    __syncthreads();

    // gi for t=0 (current-step registers)
    float g_r, g_z, g_n;
    {
        const float* gib = gi + (size_t)bown * G3 + j;
        g_r = __ldg(gib); g_z = __ldg(gib + HH); g_n = __ldg(gib + 2 * HH);
    }

    unsigned long long bar_addr;
    asm("cvta.global.u64 %0, %1;" : "=l"(bar_addr) : "l"(&g_bar));

    for (int t = 0; t < TT; t++) {
        const float* hA = g_h + (t & 1) * BH + (size_t)bp * HH;         // batch bp
        const float* hB = hA + 32 * HH;                                  // batch bp+32
        float*       hnxt = g_h + ((t + 1) & 1) * BH;

        unsigned long long accA[12], accB[12];
        #pragma unroll
        for (int r = 0; r < 12; r++) { accA[r] = 0ULL; accB[r] = 0ULL; }

        float4 bufA[2], bufB[2];
        bufA[0] = __ldcg(reinterpret_cast<const float4*>(hA + 4 * q));
        bufB[0] = __ldcg(reinterpret_cast<const float4*>(hB + 4 * q));

        #pragma unroll
        for (int xi = 0; xi < 16; xi++) {
            const int cur = xi & 1;
            if (xi < 15) {
                bufA[cur ^ 1] = __ldcg(reinterpret_cast<const float4*>(
                    hA + (xi + 1) * 32 + 4 * q));
                bufB[cur ^ 1] = __ldcg(reinterpret_cast<const float4*>(
                    hB + (xi + 1) * 32 + 4 * q));
            }
            ulonglong2 ha = *reinterpret_cast<ulonglong2*>(&bufA[cur]);
            ulonglong2 hb = *reinterpret_cast<ulonglong2*>(&bufB[cur]);
            const int base = xi * 32 + 4 * q;
            #pragma unroll
            for (int r = 0; r < 12; r++) {
                ulonglong2 w2 = *reinterpret_cast<const ulonglong2*>(
                    &w_sh[r * WPAD + base]);
                fma2(accA[r], ha.x, w2.x); fma2(accA[r], ha.y, w2.y);
                fma2(accB[r], hb.x, w2.x); fma2(accB[r], hb.y, w2.y);
            }
        }

        // Prefetch NEXT step's gi into separate registers (latency overlaps
        // the reduction + barrier). Committed to g_* only after gate math.
        float n_r, n_z, n_n;
        {
            int tn = (t + 1 < TT) ? (t + 1) : t;
            const float* gib = gi + (size_t)tn * BH3 + (size_t)bown * G3 + j;
            n_r = __ldg(gib);
            n_z = __ldg(gib + HH);
            n_n = __ldg(gib + 2 * HH);
        }

        // Fold f32x2 halves, butterfly-reduce the 8 q-lanes.
        float sA[12], sB[12];
        #pragma unroll
        for (int r = 0; r < 12; r++) {
            float2 fa = *reinterpret_cast<float2*>(&accA[r]);
            float2 fb = *reinterpret_cast<float2*>(&accB[r]);
            sA[r] = fa.x + fa.y;
            sB[r] = fb.x + fb.y;
        }
        #pragma unroll
        for (int d = 1; d <= 4; d <<= 1) {
            #pragma unroll
            for (int r = 0; r < 12; r++) {
                sA[r] += __shfl_xor_sync(0xffffffffu, sA[r], d);
                sB[r] += __shfl_xor_sync(0xffffffffu, sB[r], d);
            }
        }

        // Register-only selection (no dynamic local-array indexing):
        // pick batch (wb) per element, then column (jj) via SEL chains.
        float cr[4], cz[4], cn[4];
        #pragma unroll
        for (int i = 0; i < 4; i++) {
            cr[i] = wb ? sB[i]     : sA[i];
            cz[i] = wb ? sB[4 + i] : sA[4 + i];
            cn[i] = wb ? sB[8 + i] : sA[8 + i];
        }
        float hr = (jj == 0) ? cr[0] : (jj == 1) ? cr[1] : (jj == 2) ? cr[2] : cr[3];
        float hz = (jj == 0) ? cz[0] : (jj == 1) ? cz[1] : (jj == 2) ? cz[2] : cz[3];
        float hn = (jj == 0) ? cn[0] : (jj == 1) ? cn[1] : (jj == 2) ? cn[2] : cn[3];

        // Gate math (torch GRU order r, z, n) — uses CURRENT step's gi.
        float rr = 1.f / (1.f + __expf(-(g_r + bh_r + hr)));
        float zz = 1.f / (1.f + __expf(-(g_z + bh_z + hz)));
        float nn = tanhf(g_n + rr * (hn + bh_n));
        float hnew = nn + zz * (hreg - nn);    // (1-z)*n + z*h
        hreg = hnew;

        // Commit prefetched gi for the next iteration.
        g_r = n_r; g_z = n_z; g_n = n_n;

        __stcg(&hnxt[(size_t)bown * HH + j], hnew);
        if (outs) __stcg(&outs[(size_t)t * BH + (size_t)bown * HH + j], hnew);

        // Grid barrier: release-arrive + acquire-poll (no L1 flush).
        __syncthreads();
        if (tid == 0) {
            unsigned oldv;
            asm volatile("atom.release.gpu.global.add.u32 %0, [%1], 1;"
                         : "=r"(oldv) : "l"(bar_addr) : "memory");
            const unsigned target = (unsigned)(t + 1) * NCTA;
            unsigned v;
            do {
                asm volatile("ld.acquire.gpu.global.u32 %0, [%1];"
                             : "=r"(v) : "l"(bar_addr) : "memory");
            } while (v < target);
        }
        __syncthreads();
    }
}

// =====================================================================
// Kernel 3: out[b,o] = h_final[b,:] . fc_w[o,:] + fc_b[o]
// =====================================================================
__global__ __launch_bounds__(256) void fc_kernel(
    const float* __restrict__ hsrc,
    const float* __restrict__ fcw,
    const float* __restrict__ fcb,
    float* __restrict__ out)
{
    __shared__ float hrow[HH];
    const int b = blockIdx.x;
    const int o = threadIdx.x;
    for (int i = threadIdx.x; i < HH; i += 256)
        hrow[i] = hsrc[(size_t)b * HH + i];
    __syncthreads();

    float acc = fcb[o];
    const float4* w4 = reinterpret_cast<const float4*>(fcw + (size_t)o * HH);
    #pragma unroll 8
    for (int k4 = 0; k4 < HH / 4; k4++) {
        float4 w = w4[k4];
        acc = fmaf(hrow[k4 * 4 + 0], w.x, acc);
        acc = fmaf(hrow[k4 * 4 + 1], w.y, acc);
        acc = fmaf(hrow[k4 * 4 + 2], w.z, acc);
        acc = fmaf(hrow[k4 * 4 + 3], w.w, acc);
    }
    out[(size_t)b * OUTF + o] = acc;
}

// Kernel 4: hn = final h ; h0 = zeros
__global__ void tail_kernel(const float* __restrict__ hsrc,
                            float* __restrict__ dst_hn,
                            float* __restrict__ dst_h0,
                            int write_hn, int write_h0)
{
    int i = blockIdx.x * blockDim.x + threadIdx.x;
    if (i < BH) {
        if (write_hn) dst_hn[i] = hsrc[i];
        if (write_h0) dst_h0[i] = 0.f;
    }
}

// Profiling positioner: keeps ncu "-s 5 -c 1" landing on gru_recur_kernel
// (order: memset, memset, dummy, dummy, gi, recur).
__global__ void dummy_kernel() {}

// =====================================================================
extern "C" void kernel_launch(void* const* d_in, const int* in_sizes, int n_in,
                              void* d_out, int out_size)
{
    const float* x   = (const float*)d_in[0];
    const float* wih = (const float*)d_in[1];
    const float* whh = (const float*)d_in[2];
    const float* bih = (const float*)d_in[3];
    const float* bhh = (const float*)d_in[4];
    const float* fcw = (const float*)d_in[5];
    const float* fcb = (const float*)d_in[6];
    float* out = (float*)d_out;

    void *p_h = nullptr, *p_bar = nullptr, *p_gi = nullptr;
    cudaGetSymbolAddress(&p_h,  g_h);
    cudaGetSymbolAddress(&p_bar, g_bar);
    cudaGetSymbolAddress(&p_gi, g_gi);

    // Reset recurrence state each invocation (capturable, deterministic).
    cudaMemsetAsync(p_h,  0, sizeof(float) * 2 * BH, 0);
    cudaMemsetAsync(p_bar, 0, sizeof(unsigned), 0);

    dummy_kernel<<<1, 32>>>();
    dummy_kernel<<<1, 32>>>();

    // Phase 1: input-side projections
    dim3 gg(G3 / 64, (TT * BB) / 128);   // (24, 512)
    gi_gemm_kernel<<<gg, 256>>>(x, wih, bih, (float*)p_gi);

    // Output layout: concatenation of (outs[T,B,H], out[B,OUT], hn[B,H], h0[B,H])
    const long long OUTS_N = (long long)TT * BH;
    long long remaining = (long long)out_size;
    float* outs_dst = nullptr;
    long long off = 0;
    if (remaining >= OUTS_N) { outs_dst = out; off = OUTS_N; }

    // Phase 2: recurrence (final h lands in g_h[0..BH) since T is even)
    gru_recur_kernel<<<NCTA, 256>>>(whh, bhh, (const float*)p_gi, outs_dst);

    const float* hfinal = (const float*)p_h;

    // Phase 3: epilogue outputs
    if (remaining - off >= (long long)BB * OUTF) {
        fc_kernel<<<BB, 256>>>(hfinal, fcw, fcb, out + off);
        off += (long long)BB * OUTF;
    } else if (remaining == (long long)BB * OUTF) {
        fc_kernel<<<BB, 256>>>(hfinal, fcw, fcb, out);
        off = remaining;
    }
    int wh = (remaining - off >= (long long)BH) ? 1 : 0;
    int w0 = (remaining - off >= (long long)2 * BH) ? 1 : 0;
    if (wh) {
        tail_kernel<<<(BH + 255) / 256, 256>>>(hfinal,
                                               out + off,
                                               out + off + BH,
                                               wh, w0);
    }
}